// round 4
// baseline (speedup 1.0000x reference)
#include <cuda_runtime.h>
#include <math.h>

// Problem constants
#define Bq   2
#define Sq   2048
#define HIDq 4096
#define Hq   32
#define KVq  8
#define Dq   128
#define Gq   (Hq / KVq)

// Scratch buffers (allocation-free rule: __device__ globals)
__device__ float g_proj[(size_t)Bq * Sq * Hq * Dq];  // staging: raw projection [B*S, Hh*D]
__device__ float g_q[(size_t)Bq * Hq * Sq * Dq];     // [B,H,S,D]
__device__ float g_k[(size_t)Bq * KVq * Sq * Dq];    // [B,KV,S,D]
__device__ float g_v[(size_t)Bq * KVq * Sq * Dq];    // [B,KV,S,D]
__device__ float g_attn[(size_t)Bq * Sq * Hq * Dq];  // [B,S,H*D]

// ---------------------------------------------------------------------------
// Naive NT GEMM: C[m,n] = sum_k A[m,k] * W[n,k]
// A: [M,K] row-major, W: [N,K] row-major, C: [M,N] row-major.
// Block = 32x32 threads, one output per thread, 32-wide k tiles.
// asel: 0 -> A = Aparam, 1 -> A = g_attn
// csel: 0 -> C = Cparam, 1 -> C = g_proj
// All of M, N, K are multiples of 32 here (4096/1024/4096).
// ---------------------------------------------------------------------------
__global__ __launch_bounds__(1024)
void gemm_naive(const float* __restrict__ Aparam, const float* __restrict__ W,
                float* __restrict__ Cparam, int M, int N, int K,
                int asel, int csel)
{
    __shared__ float As[32][33];
    __shared__ float Ws[32][33];

    const float* A = (asel == 1) ? g_attn : Aparam;
    float* C = (csel == 1) ? g_proj : Cparam;

    const int tx = threadIdx.x;   // 0..31
    const int ty = threadIdx.y;   // 0..31
    const int m = blockIdx.y * 32 + ty;
    const int n = blockIdx.x * 32 + tx;

    float acc = 0.f;
    for (int k0 = 0; k0 < K; k0 += 32) {
        As[ty][tx] = A[(size_t)m * K + k0 + tx];
        Ws[ty][tx] = W[(size_t)(blockIdx.x * 32 + ty) * K + k0 + tx];
        __syncthreads();
#pragma unroll
        for (int kk = 0; kk < 32; kk++)
            acc += As[ty][kk] * Ws[tx][kk];
        __syncthreads();
    }
    C[(size_t)m * N + n] = acc;
}

// ---------------------------------------------------------------------------
// RoPE + transpose: in = g_proj [B*S, Hh*D] -> out [B, Hh, S, D].
// One thread per (even,odd) pair. rope=0 -> plain transpose (for V).
// out[..., 2i]   = x[2i]*cos - x[2i+1]*sin
// out[..., 2i+1] = x[2i+1]*cos + x[2i]*sin      (cos[2i]==cos[2i+1])
// dsel: 0 -> g_q, 1 -> g_k, 2 -> g_v
// ---------------------------------------------------------------------------
__global__ __launch_bounds__(256)
void rope_transpose(const float* __restrict__ cosp, const float* __restrict__ sinp,
                    int Hh, int rope, int dsel, size_t total_pairs)
{
    size_t idx = (size_t)blockIdx.x * blockDim.x + threadIdx.x;
    if (idx >= total_pairs) return;

    const int dpair = (int)(idx % (Dq / 2));
    size_t rest = idx / (Dq / 2);
    const int hh = (int)(rest % Hh);  rest /= Hh;
    const int s  = (int)(rest % Sq);
    const int b  = (int)(rest / Sq);
    const int d  = dpair * 2;

    const size_t src = ((size_t)(b * Sq + s) * Hh + hh) * Dq + d;
    float v0 = g_proj[src];
    float v1 = g_proj[src + 1];
    if (rope) {
        const float c  = cosp[s * Dq + d];
        const float sn = sinp[s * Dq + d];
        const float t0 = v0 * c - v1 * sn;
        const float t1 = v1 * c + v0 * sn;
        v0 = t0; v1 = t1;
    }
    float* dst = (dsel == 0) ? g_q : (dsel == 1) ? g_k : g_v;
    const size_t o = (((size_t)b * Hh + hh) * Sq + s) * Dq + d;
    dst[o]     = v0;
    dst[o + 1] = v1;
}

// ---------------------------------------------------------------------------
// Naive causal attention, two-pass softmax. One block per (s, h, b) query row.
// 128 threads. Thread tid owns output dim d = tid in pass B.
// ---------------------------------------------------------------------------
__global__ __launch_bounds__(128)
void attn_naive()
{
    const int s = blockIdx.x;
    const int h = blockIdx.y;
    const int b = blockIdx.z;
    const int kh = h / Gq;
    const int tid = threadIdx.x;
    const float scale = 0.08838834764831845f;  // 1/sqrt(128)

    __shared__ float qrow[128];
    __shared__ float pbuf[128];
    __shared__ float red[128];

    const float* Qr = g_q + (((size_t)b * Hq + h) * Sq + s) * Dq;
    const float* Kb = g_k + ((size_t)b * KVq + kh) * Sq * Dq;
    const float* Vb = g_v + ((size_t)b * KVq + kh) * Sq * Dq;

    qrow[tid] = Qr[tid];
    __syncthreads();

    // Pass A: row max of masked scores
    float mloc = -INFINITY;
    for (int t0 = 0; t0 <= s; t0 += 128) {
        const int t = t0 + tid;
        if (t <= s) {
            const float* Kr = Kb + (size_t)t * Dq;
            float acc = 0.f;
            for (int d = 0; d < 128; d++) acc += qrow[d] * Kr[d];
            mloc = fmaxf(mloc, acc * scale);
        }
    }
    red[tid] = mloc;
    __syncthreads();
    for (int off = 64; off > 0; off >>= 1) {
        if (tid < off) red[tid] = fmaxf(red[tid], red[tid + off]);
        __syncthreads();
    }
    const float m = red[0];
    __syncthreads();

    // Pass B: probabilities, running sum, output accumulation
    float oacc = 0.f;
    float lloc = 0.f;
    for (int t0 = 0; t0 <= s; t0 += 128) {
        const int t = t0 + tid;
        float p = 0.f;
        if (t <= s) {
            const float* Kr = Kb + (size_t)t * Dq;
            float acc = 0.f;
            for (int d = 0; d < 128; d++) acc += qrow[d] * Kr[d];
            p = expf(acc * scale - m);
        }
        pbuf[tid] = p;
        lloc += p;
        __syncthreads();
        const int jmax = min(128, s - t0 + 1);
        const float* Vr = Vb + (size_t)t0 * Dq;
        for (int j = 0; j < jmax; j++)
            oacc += pbuf[j] * Vr[(size_t)j * Dq + tid];
        __syncthreads();
    }
    red[tid] = lloc;
    __syncthreads();
    for (int off = 64; off > 0; off >>= 1) {
        if (tid < off) red[tid] += red[tid + off];
        __syncthreads();
    }
    const float l = red[0];

    g_attn[((size_t)(b * Sq + s) * Hq + h) * Dq + tid] = oacc / l;
}

// ---------------------------------------------------------------------------
// Launcher
// (Resubmission of the R2 bisect pipeline — R3 run was lost to a container
// infra failure, so this experiment has produced no data yet.)
// ---------------------------------------------------------------------------
extern "C" void kernel_launch(void* const* d_in, const int* in_sizes, int n_in,
                              void* d_out, int out_size)
{
    // Input mapping (dict order confirmed: first input has B*S*HID elements).
    const float *hs, *cosp, *sinp, *wq, *wk, *wv, *wo;
    if (in_sizes[0] == Bq * Sq * HIDq) {
        hs   = (const float*)d_in[0];
        cosp = (const float*)d_in[1];
        sinp = (const float*)d_in[2];
        wq   = (const float*)d_in[3];
        wk   = (const float*)d_in[4];
        wv   = (const float*)d_in[5];
        wo   = (const float*)d_in[6];
    } else {  // alphabetical fallback
        cosp = (const float*)d_in[0];
        hs   = (const float*)d_in[1];
        sinp = (const float*)d_in[2];
        wk   = (const float*)d_in[3];
        wo   = (const float*)d_in[4];
        wq   = (const float*)d_in[5];
        wv   = (const float*)d_in[6];
    }
    float* out = (float*)d_out;

    const dim3 blk2(32, 32);
    const int M = Bq * Sq;          // 4096
    const int NQ = Hq * Dq;         // 4096
    const int NKV = KVq * Dq;       // 1024

    // Q projection -> g_proj, then RoPE+transpose -> g_q
    gemm_naive<<<dim3(NQ / 32, M / 32), blk2>>>(hs, wq, nullptr, M, NQ, HIDq, 0, 1);
    {
        size_t pairs = (size_t)Bq * Sq * Hq * (Dq / 2);
        rope_transpose<<<(unsigned)((pairs + 255) / 256), 256>>>(cosp, sinp, Hq, 1, 0, pairs);
    }
    // K projection -> g_proj, then RoPE+transpose -> g_k
    gemm_naive<<<dim3(NKV / 32, M / 32), blk2>>>(hs, wk, nullptr, M, NKV, HIDq, 0, 1);
    {
        size_t pairs = (size_t)Bq * Sq * KVq * (Dq / 2);
        rope_transpose<<<(unsigned)((pairs + 255) / 256), 256>>>(cosp, sinp, KVq, 1, 1, pairs);
    }
    // V projection -> g_proj, then transpose -> g_v
    gemm_naive<<<dim3(NKV / 32, M / 32), blk2>>>(hs, wv, nullptr, M, NKV, HIDq, 0, 1);
    {
        size_t pairs = (size_t)Bq * Sq * KVq * (Dq / 2);
        rope_transpose<<<(unsigned)((pairs + 255) / 256), 256>>>(cosp, sinp, KVq, 0, 2, pairs);
    }

    // Attention -> g_attn
    attn_naive<<<dim3(Sq, Hq, Bq), 128>>>();

    // Output projection: out = g_attn @ wo^T
    gemm_naive<<<dim3(HIDq / 32, M / 32), blk2>>>(nullptr, wo, out, M, HIDq, NQ, 1, 0);
}

// round 5
// speedup vs baseline: 1.1748x; 1.1748x over previous
#include <cuda_runtime.h>
#include <math.h>

// Problem constants
#define Bq   2
#define Sq   2048
#define HIDq 4096
#define Hq   32
#define KVq  8
#define Dq   128
#define Gq   (Hq / KVq)

// Scratch buffers (allocation-free rule: __device__ globals)
__device__ float g_proj[(size_t)Bq * Sq * Hq * Dq];  // staging: raw projection [B*S, Hh*D]
__device__ float g_q[(size_t)Bq * Hq * Sq * Dq];     // [B,H,S,D]
__device__ float g_k[(size_t)Bq * KVq * Sq * Dq];    // [B,KV,S,D]
__device__ float g_v[(size_t)Bq * KVq * Sq * Dq];    // [B,KV,S,D]
__device__ float g_attn[(size_t)Bq * Sq * Hq * Dq];  // [B,S,H*D]

// ---------------------------------------------------------------------------
// Fast NT GEMM: C[m,n] = sum_k A[m,k] * W[n,k]
// A: [M,K] row-major, W: [N,K] row-major, C: [M,N] row-major.
// BM=BN=128, BK=8, 256 threads, 8x8 per-thread microkernel.
// asel: 1 -> A = g_attn. csel: 1 -> C = g_proj.
// M, N multiples of 128; K multiple of 8.
// ---------------------------------------------------------------------------
__global__ __launch_bounds__(256)
void gemm_fast(const float* __restrict__ Aparam, const float* __restrict__ W,
               float* __restrict__ Cparam, int M, int N, int K,
               int asel, int csel)
{
    __shared__ float As[8][128];   // As[k][m]
    __shared__ float Bs[8][128];   // Bs[k][n]

    const float* A = (asel == 1) ? g_attn : Aparam;
    float* C = (csel == 1) ? g_proj : Cparam;

    const int tid = threadIdx.x;
    const int m0 = blockIdx.y * 128;
    const int n0 = blockIdx.x * 128;

    // Load mapping: thread -> (row = tid/2, kcol = (tid&1)*4), float4 each.
    const int lrow = tid >> 1;          // 0..127
    const int lk   = (tid & 1) * 4;     // 0 or 4
    const float* Ald = A + (size_t)(m0 + lrow) * K + lk;
    const float* Wld = W + (size_t)(n0 + lrow) * K + lk;

    // Compute mapping: 8x8 tile at (tm, tn).
    const int tm = (tid >> 4) << 3;     // 0,8,...,120
    const int tn = (tid & 15) << 3;     // 0,8,...,120

    float acc[8][8];
#pragma unroll
    for (int i = 0; i < 8; i++)
#pragma unroll
        for (int j = 0; j < 8; j++) acc[i][j] = 0.f;

    for (int k0 = 0; k0 < K; k0 += 8) {
        const float4 av = *(const float4*)(Ald + k0);
        const float4 wv = *(const float4*)(Wld + k0);
        __syncthreads();   // previous iteration's reads complete
        As[lk + 0][lrow] = av.x;
        As[lk + 1][lrow] = av.y;
        As[lk + 2][lrow] = av.z;
        As[lk + 3][lrow] = av.w;
        Bs[lk + 0][lrow] = wv.x;
        Bs[lk + 1][lrow] = wv.y;
        Bs[lk + 2][lrow] = wv.z;
        Bs[lk + 3][lrow] = wv.w;
        __syncthreads();
#pragma unroll
        for (int k = 0; k < 8; k++) {
            float a[8], b[8];
#pragma unroll
            for (int i = 0; i < 8; i++) a[i] = As[k][tm + i];
#pragma unroll
            for (int j = 0; j < 8; j++) b[j] = Bs[k][tn + j];
#pragma unroll
            for (int i = 0; i < 8; i++)
#pragma unroll
                for (int j = 0; j < 8; j++) acc[i][j] += a[i] * b[j];
        }
    }

    // Epilogue: plain write (float4-vectorized).
#pragma unroll
    for (int i = 0; i < 8; i++) {
        float* crow = C + (size_t)(m0 + tm + i) * N + (n0 + tn);
#pragma unroll
        for (int j = 0; j < 8; j += 4) {
            float4 v;
            v.x = acc[i][j + 0];
            v.y = acc[i][j + 1];
            v.z = acc[i][j + 2];
            v.w = acc[i][j + 3];
            *(float4*)(crow + j) = v;
        }
    }
}

// ---------------------------------------------------------------------------
// RoPE + transpose: in = g_proj [B*S, Hh*D] -> out [B, Hh, S, D].
// One thread per (even,odd) pair. rope=0 -> plain transpose (for V).
// dsel: 0 -> g_q, 1 -> g_k, 2 -> g_v
// ---------------------------------------------------------------------------
__global__ __launch_bounds__(256)
void rope_transpose(const float* __restrict__ cosp, const float* __restrict__ sinp,
                    int Hh, int rope, int dsel, size_t total_pairs)
{
    size_t idx = (size_t)blockIdx.x * blockDim.x + threadIdx.x;
    if (idx >= total_pairs) return;

    const int dpair = (int)(idx % (Dq / 2));
    size_t rest = idx / (Dq / 2);
    const int hh = (int)(rest % Hh);  rest /= Hh;
    const int s  = (int)(rest % Sq);
    const int b  = (int)(rest / Sq);
    const int d  = dpair * 2;

    const size_t src = ((size_t)(b * Sq + s) * Hh + hh) * Dq + d;
    float v0 = g_proj[src];
    float v1 = g_proj[src + 1];
    if (rope) {
        const float c  = cosp[s * Dq + d];
        const float sn = sinp[s * Dq + d];
        const float t0 = v0 * c - v1 * sn;
        const float t1 = v1 * c + v0 * sn;
        v0 = t0; v1 = t1;
    }
    float* dst = (dsel == 0) ? g_q : (dsel == 1) ? g_k : g_v;
    const size_t o = (((size_t)b * Hh + hh) * Sq + s) * Dq + d;
    dst[o]     = v0;
    dst[o + 1] = v1;
}

// ---------------------------------------------------------------------------
// Naive causal attention, two-pass softmax. One block per (s, h, b) query row.
// 128 threads. (Unchanged from the passing R4 baseline.)
// ---------------------------------------------------------------------------
__global__ __launch_bounds__(128)
void attn_naive()
{
    const int s = blockIdx.x;
    const int h = blockIdx.y;
    const int b = blockIdx.z;
    const int kh = h / Gq;
    const int tid = threadIdx.x;
    const float scale = 0.08838834764831845f;  // 1/sqrt(128)

    __shared__ float qrow[128];
    __shared__ float pbuf[128];
    __shared__ float red[128];

    const float* Qr = g_q + (((size_t)b * Hq + h) * Sq + s) * Dq;
    const float* Kb = g_k + ((size_t)b * KVq + kh) * Sq * Dq;
    const float* Vb = g_v + ((size_t)b * KVq + kh) * Sq * Dq;

    qrow[tid] = Qr[tid];
    __syncthreads();

    // Pass A: row max of masked scores
    float mloc = -INFINITY;
    for (int t0 = 0; t0 <= s; t0 += 128) {
        const int t = t0 + tid;
        if (t <= s) {
            const float* Kr = Kb + (size_t)t * Dq;
            float acc = 0.f;
            for (int d = 0; d < 128; d++) acc += qrow[d] * Kr[d];
            mloc = fmaxf(mloc, acc * scale);
        }
    }
    red[tid] = mloc;
    __syncthreads();
    for (int off = 64; off > 0; off >>= 1) {
        if (tid < off) red[tid] = fmaxf(red[tid], red[tid + off]);
        __syncthreads();
    }
    const float m = red[0];
    __syncthreads();

    // Pass B: probabilities, running sum, output accumulation
    float oacc = 0.f;
    float lloc = 0.f;
    for (int t0 = 0; t0 <= s; t0 += 128) {
        const int t = t0 + tid;
        float p = 0.f;
        if (t <= s) {
            const float* Kr = Kb + (size_t)t * Dq;
            float acc = 0.f;
            for (int d = 0; d < 128; d++) acc += qrow[d] * Kr[d];
            p = expf(acc * scale - m);
        }
        pbuf[tid] = p;
        lloc += p;
        __syncthreads();
        const int jmax = min(128, s - t0 + 1);
        const float* Vr = Vb + (size_t)t0 * Dq;
        for (int j = 0; j < jmax; j++)
            oacc += pbuf[j] * Vr[(size_t)j * Dq + tid];
        __syncthreads();
    }
    red[tid] = lloc;
    __syncthreads();
    for (int off = 64; off > 0; off >>= 1) {
        if (tid < off) red[tid] += red[tid + off];
        __syncthreads();
    }
    const float l = red[0];

    g_attn[((size_t)(b * Sq + s) * Hq + h) * Dq + tid] = oacc / l;
}

// ---------------------------------------------------------------------------
// Launcher
// ---------------------------------------------------------------------------
extern "C" void kernel_launch(void* const* d_in, const int* in_sizes, int n_in,
                              void* d_out, int out_size)
{
    const float *hs, *cosp, *sinp, *wq, *wk, *wv, *wo;
    if (in_sizes[0] == Bq * Sq * HIDq) {
        hs   = (const float*)d_in[0];
        cosp = (const float*)d_in[1];
        sinp = (const float*)d_in[2];
        wq   = (const float*)d_in[3];
        wk   = (const float*)d_in[4];
        wv   = (const float*)d_in[5];
        wo   = (const float*)d_in[6];
    } else {  // alphabetical fallback
        cosp = (const float*)d_in[0];
        hs   = (const float*)d_in[1];
        sinp = (const float*)d_in[2];
        wk   = (const float*)d_in[3];
        wo   = (const float*)d_in[4];
        wq   = (const float*)d_in[5];
        wv   = (const float*)d_in[6];
    }
    float* out = (float*)d_out;

    const dim3 blk(256);
    const int M = Bq * Sq;          // 4096
    const int NQ = Hq * Dq;         // 4096
    const int NKV = KVq * Dq;       // 1024

    // Q projection -> g_proj, then RoPE+transpose -> g_q
    gemm_fast<<<dim3(NQ / 128, M / 128), blk>>>(hs, wq, nullptr, M, NQ, HIDq, 0, 1);
    {
        size_t pairs = (size_t)Bq * Sq * Hq * (Dq / 2);
        rope_transpose<<<(unsigned)((pairs + 255) / 256), 256>>>(cosp, sinp, Hq, 1, 0, pairs);
    }
    // K projection -> g_proj, then RoPE+transpose -> g_k
    gemm_fast<<<dim3(NKV / 128, M / 128), blk>>>(hs, wk, nullptr, M, NKV, HIDq, 0, 1);
    {
        size_t pairs = (size_t)Bq * Sq * KVq * (Dq / 2);
        rope_transpose<<<(unsigned)((pairs + 255) / 256), 256>>>(cosp, sinp, KVq, 1, 1, pairs);
    }
    // V projection -> g_proj, then transpose -> g_v
    gemm_fast<<<dim3(NKV / 128, M / 128), blk>>>(hs, wv, nullptr, M, NKV, HIDq, 0, 1);
    {
        size_t pairs = (size_t)Bq * Sq * KVq * (Dq / 2);
        rope_transpose<<<(unsigned)((pairs + 255) / 256), 256>>>(cosp, sinp, KVq, 0, 2, pairs);
    }

    // Attention -> g_attn
    attn_naive<<<dim3(Sq, Hq, Bq), 128>>>();

    // Output projection: out = g_attn @ wo^T
    gemm_fast<<<dim3(HIDq / 128, M / 128), blk>>>(nullptr, wo, out, M, HIDq, NQ, 1, 0);
}

// round 9
// speedup vs baseline: 9.3618x; 7.9690x over previous
#include <cuda_runtime.h>
#include <math.h>

// Problem constants
#define Bq   2
#define Sq   2048
#define HIDq 4096
#define Hq   32
#define KVq  8
#define Dq   128
#define Gq   (Hq / KVq)

// Scratch buffers (allocation-free rule: __device__ globals)
__device__ float g_proj[(size_t)Bq * Sq * Hq * Dq];  // staging: raw projection [B*S, Hh*D]
__device__ float g_q[(size_t)Bq * Hq * Sq * Dq];     // [B,H,S,D]
__device__ float g_k[(size_t)Bq * KVq * Sq * Dq];    // [B,KV,S,D]
__device__ float g_v[(size_t)Bq * KVq * Sq * Dq];    // [B,KV,S,D]
__device__ float g_attn[(size_t)Bq * Sq * Hq * Dq];  // [B,S,H*D]

// ---------------------------------------------------------------------------
// Fast NT GEMM (unchanged from R5 - PASSING)
// ---------------------------------------------------------------------------
__global__ __launch_bounds__(256)
void gemm_fast(const float* __restrict__ Aparam, const float* __restrict__ W,
               float* __restrict__ Cparam, int M, int N, int K,
               int asel, int csel)
{
    __shared__ float As[8][128];   // As[k][m]
    __shared__ float Bs[8][128];   // Bs[k][n]

    const float* A = (asel == 1) ? g_attn : Aparam;
    float* C = (csel == 1) ? g_proj : Cparam;

    const int tid = threadIdx.x;
    const int m0 = blockIdx.y * 128;
    const int n0 = blockIdx.x * 128;

    const int lrow = tid >> 1;          // 0..127
    const int lk   = (tid & 1) * 4;     // 0 or 4
    const float* Ald = A + (size_t)(m0 + lrow) * K + lk;
    const float* Wld = W + (size_t)(n0 + lrow) * K + lk;

    const int tm = (tid >> 4) << 3;     // 0,8,...,120
    const int tn = (tid & 15) << 3;     // 0,8,...,120

    float acc[8][8];
#pragma unroll
    for (int i = 0; i < 8; i++)
#pragma unroll
        for (int j = 0; j < 8; j++) acc[i][j] = 0.f;

    for (int k0 = 0; k0 < K; k0 += 8) {
        const float4 av = *(const float4*)(Ald + k0);
        const float4 wv = *(const float4*)(Wld + k0);
        __syncthreads();
        As[lk + 0][lrow] = av.x;
        As[lk + 1][lrow] = av.y;
        As[lk + 2][lrow] = av.z;
        As[lk + 3][lrow] = av.w;
        Bs[lk + 0][lrow] = wv.x;
        Bs[lk + 1][lrow] = wv.y;
        Bs[lk + 2][lrow] = wv.z;
        Bs[lk + 3][lrow] = wv.w;
        __syncthreads();
#pragma unroll
        for (int k = 0; k < 8; k++) {
            float a[8], b[8];
#pragma unroll
            for (int i = 0; i < 8; i++) a[i] = As[k][tm + i];
#pragma unroll
            for (int j = 0; j < 8; j++) b[j] = Bs[k][tn + j];
#pragma unroll
            for (int i = 0; i < 8; i++)
#pragma unroll
                for (int j = 0; j < 8; j++) acc[i][j] += a[i] * b[j];
        }
    }

#pragma unroll
    for (int i = 0; i < 8; i++) {
        float* crow = C + (size_t)(m0 + tm + i) * N + (n0 + tn);
#pragma unroll
        for (int j = 0; j < 8; j += 4) {
            float4 v;
            v.x = acc[i][j + 0];
            v.y = acc[i][j + 1];
            v.z = acc[i][j + 2];
            v.w = acc[i][j + 3];
            *(float4*)(crow + j) = v;
        }
    }
}

// ---------------------------------------------------------------------------
// RoPE + transpose (unchanged from R5 - PASSING)
// ---------------------------------------------------------------------------
__global__ __launch_bounds__(256)
void rope_transpose(const float* __restrict__ cosp, const float* __restrict__ sinp,
                    int Hh, int rope, int dsel, size_t total_pairs)
{
    size_t idx = (size_t)blockIdx.x * blockDim.x + threadIdx.x;
    if (idx >= total_pairs) return;

    const int dpair = (int)(idx % (Dq / 2));
    size_t rest = idx / (Dq / 2);
    const int hh = (int)(rest % Hh);  rest /= Hh;
    const int s  = (int)(rest % Sq);
    const int b  = (int)(rest / Sq);
    const int d  = dpair * 2;

    const size_t src = ((size_t)(b * Sq + s) * Hh + hh) * Dq + d;
    float v0 = g_proj[src];
    float v1 = g_proj[src + 1];
    if (rope) {
        const float c  = cosp[s * Dq + d];
        const float sn = sinp[s * Dq + d];
        const float t0 = v0 * c - v1 * sn;
        const float t1 = v1 * c + v0 * sn;
        v0 = t0; v1 = t1;
    }
    float* dst = (dsel == 0) ? g_q : (dsel == 1) ? g_k : g_v;
    const size_t o = (((size_t)b * Hh + hh) * Sq + s) * Dq + d;
    dst[o]     = v0;
    dst[o + 1] = v1;
}

// ---------------------------------------------------------------------------
// Flash attention v3. Identical structure to v2, with the CORRECT leading
// dimension: rows are 128 floats wide, so LDP = 130 (was 65 => row overflow,
// the root cause of every failed flash variant).
// Br=64, Bc=32, 256 threads. Thread t = (row r=t>>2, quarter q=t&3) uniformly.
// Dynamic smem: Qs[64*LDP] + Ks[32*LDP] + Vs[32*128] = 66,304 bytes.
// grid = (S/64, H, B)
// ---------------------------------------------------------------------------
#define LDP 130
#define FLASH_FLOATS (64 * LDP + 32 * LDP + 32 * 128)

__global__ __launch_bounds__(256)
void flash_v3()
{
    extern __shared__ float sm[];
    float* Qs = sm;                  // [64][LDP]
    float* Ks = Qs + 64 * LDP;       // [32][LDP]; after scores reused as P[c][r]
    float* Vs = Ks + 32 * LDP;       // [32][128]

    const int qb = blockIdx.x;
    const int h  = blockIdx.y;
    const int b  = blockIdx.z;
    const int kh = h / Gq;
    const int tid = threadIdx.x;
    const int r = tid >> 2;          // query row 0..63
    const int q = tid & 3;           // quarter 0..3
    const float scale = 0.08838834764831845f;  // 1/sqrt(128)

    const float* Qg = g_q + (((size_t)b * Hq  + h ) * Sq + (size_t)qb * 64) * Dq;
    const float* Kg = g_k + (((size_t)b * KVq + kh) * Sq) * Dq;
    const float* Vg = g_v + (((size_t)b * KVq + kh) * Sq) * Dq;

    // Load Q tile (64x128), coalesced
#pragma unroll
    for (int i = 0; i < 8; i++) {
        const int idx = tid + i * 256;
        const int rr = idx >> 5;
        const int c4 = (idx & 31) << 2;
        float4 v = *(const float4*)(Qg + rr * Dq + c4);
        Qs[rr * LDP + c4 + 0] = v.x;
        Qs[rr * LDP + c4 + 1] = v.y;
        Qs[rr * LDP + c4 + 2] = v.z;
        Qs[rr * LDP + c4 + 3] = v.w;
    }

    float m_i = -INFINITY;
    float l_i = 0.f;
    float o[32];
#pragma unroll
    for (int j = 0; j < 32; j++) o[j] = 0.f;

    const int qr = qb * 64 + r;
    const int ntiles = 2 * qb + 2;   // 32-wide key tiles covering 0..qb*64+63

    for (int cb = 0; cb < ntiles; cb++) {
        __syncthreads();   // prev tile fully consumed; Q visible at cb=0
        // Load K,V tiles (32x128 each)
#pragma unroll
        for (int i = 0; i < 4; i++) {
            const int idx = tid + i * 256;
            const int rr = idx >> 5;
            const int c4 = (idx & 31) << 2;
            float4 kv = *(const float4*)(Kg + (size_t)(cb * 32 + rr) * Dq + c4);
            Ks[rr * LDP + c4 + 0] = kv.x;
            Ks[rr * LDP + c4 + 1] = kv.y;
            Ks[rr * LDP + c4 + 2] = kv.z;
            Ks[rr * LDP + c4 + 3] = kv.w;
            float4 vv = *(const float4*)(Vg + (size_t)(cb * 32 + rr) * Dq + c4);
            *(float4*)(Vs + rr * 128 + c4) = vv;
        }
        __syncthreads();

        // Scores: thread (r,q) computes S[r][c], c = q*8..q*8+7, in registers.
        float s8[8];
#pragma unroll
        for (int j = 0; j < 8; j++) s8[j] = 0.f;
        const float* qrow = Qs + r * LDP;
#pragma unroll 4
        for (int k = 0; k < 128; k++) {
            const float qv = qrow[k];
#pragma unroll
            for (int j = 0; j < 8; j++)
                s8[j] += qv * Ks[(q * 8 + j) * LDP + k];
        }
        __syncthreads();   // all score reads of Ks done before it becomes P

        // Online softmax (row state replicated across the 4 q-threads)
        float mx = -INFINITY;
#pragma unroll
        for (int j = 0; j < 8; j++) {
            const int kc = cb * 32 + q * 8 + j;
            s8[j] = (kc <= qr) ? s8[j] * scale : -INFINITY;
            mx = fmaxf(mx, s8[j]);
        }
        mx = fmaxf(mx, __shfl_xor_sync(0xffffffffu, mx, 1));
        mx = fmaxf(mx, __shfl_xor_sync(0xffffffffu, mx, 2));
        const float m_new = fmaxf(m_i, mx);
        const float corr  = __expf(m_i - m_new);
        float lsum = 0.f;
#pragma unroll
        for (int j = 0; j < 8; j++) {
            s8[j] = __expf(s8[j] - m_new);
            lsum += s8[j];
        }
        lsum += __shfl_xor_sync(0xffffffffu, lsum, 1);
        lsum += __shfl_xor_sync(0xffffffffu, lsum, 2);
        l_i = l_i * corr + lsum;
        m_i = m_new;
#pragma unroll
        for (int j = 0; j < 32; j++) o[j] *= corr;
        // Stage P into the dead K tile: P[c][r] at Ks[c*LDP + r] (r<64 < LDP)
#pragma unroll
        for (int j = 0; j < 8; j++)
            Ks[(q * 8 + j) * LDP + r] = s8[j];
        __syncthreads();   // P visible to all threads

        // PV: thread (r,q) owns d = j*16 + q*4 + e (j=0..7, e=0..3)
        for (int c = 0; c < 32; c++) {
            const float pv = Ks[c * LDP + r];
            const float* vrow = Vs + c * 128 + q * 4;
#pragma unroll
            for (int j = 0; j < 8; j++) {
                float4 v4 = *(const float4*)(vrow + j * 16);
                o[j * 4 + 0] += pv * v4.x;
                o[j * 4 + 1] += pv * v4.y;
                o[j * 4 + 2] += pv * v4.z;
                o[j * 4 + 3] += pv * v4.w;
            }
        }
    }

    // Finalize + write to [B, S, H*D]; d = j*16 + q*4 + e
    const float inv = 1.f / l_i;
    float* og = g_attn + ((size_t)(b * Sq + qr) * Hq + h) * Dq + q * 4;
#pragma unroll
    for (int j = 0; j < 8; j++) {
        float4 v;
        v.x = o[j * 4 + 0] * inv;
        v.y = o[j * 4 + 1] * inv;
        v.z = o[j * 4 + 2] * inv;
        v.w = o[j * 4 + 3] * inv;
        *(float4*)(og + j * 16) = v;
    }
}

// ---------------------------------------------------------------------------
// Launcher
// ---------------------------------------------------------------------------
extern "C" void kernel_launch(void* const* d_in, const int* in_sizes, int n_in,
                              void* d_out, int out_size)
{
    const float *hs, *cosp, *sinp, *wq, *wk, *wv, *wo;
    if (in_sizes[0] == Bq * Sq * HIDq) {
        hs   = (const float*)d_in[0];
        cosp = (const float*)d_in[1];
        sinp = (const float*)d_in[2];
        wq   = (const float*)d_in[3];
        wk   = (const float*)d_in[4];
        wv   = (const float*)d_in[5];
        wo   = (const float*)d_in[6];
    } else {  // alphabetical fallback
        cosp = (const float*)d_in[0];
        hs   = (const float*)d_in[1];
        sinp = (const float*)d_in[2];
        wk   = (const float*)d_in[3];
        wo   = (const float*)d_in[4];
        wq   = (const float*)d_in[5];
        wv   = (const float*)d_in[6];
    }
    float* out = (float*)d_out;

    const dim3 blk(256);
    const int M = Bq * Sq;          // 4096
    const int NQ = Hq * Dq;         // 4096
    const int NKV = KVq * Dq;       // 1024

    // Q projection -> g_proj, then RoPE+transpose -> g_q
    gemm_fast<<<dim3(NQ / 128, M / 128), blk>>>(hs, wq, nullptr, M, NQ, HIDq, 0, 1);
    {
        size_t pairs = (size_t)Bq * Sq * Hq * (Dq / 2);
        rope_transpose<<<(unsigned)((pairs + 255) / 256), 256>>>(cosp, sinp, Hq, 1, 0, pairs);
    }
    // K projection -> g_proj, then RoPE+transpose -> g_k
    gemm_fast<<<dim3(NKV / 128, M / 128), blk>>>(hs, wk, nullptr, M, NKV, HIDq, 0, 1);
    {
        size_t pairs = (size_t)Bq * Sq * KVq * (Dq / 2);
        rope_transpose<<<(unsigned)((pairs + 255) / 256), 256>>>(cosp, sinp, KVq, 1, 1, pairs);
    }
    // V projection -> g_proj, then transpose -> g_v
    gemm_fast<<<dim3(NKV / 128, M / 128), blk>>>(hs, wv, nullptr, M, NKV, HIDq, 0, 1);
    {
        size_t pairs = (size_t)Bq * Sq * KVq * (Dq / 2);
        rope_transpose<<<(unsigned)((pairs + 255) / 256), 256>>>(cosp, sinp, KVq, 0, 2, pairs);
    }

    // Flash attention v3 -> g_attn
    const int smem_bytes = FLASH_FLOATS * (int)sizeof(float);  // 66,304
    cudaFuncSetAttribute(flash_v3, cudaFuncAttributeMaxDynamicSharedMemorySize,
                         smem_bytes);
    flash_v3<<<dim3(Sq / 64, Hq, Bq), blk, smem_bytes>>>();

    // Output projection: out = g_attn @ wo^T
    gemm_fast<<<dim3(HIDq / 128, M / 128), blk>>>(nullptr, wo, out, M, HIDq, NQ, 1, 0);
}

// round 10
// speedup vs baseline: 15.2700x; 1.6311x over previous
#include <cuda_runtime.h>
#include <math.h>
#include <stdint.h>

// Problem constants
#define Bq   2
#define Sq   2048
#define HIDq 4096
#define Hq   32
#define KVq  8
#define Dq   128
#define Gq   (Hq / KVq)

// Scratch buffers (allocation-free rule: __device__ globals)
__device__ float g_proj[(size_t)Bq * Sq * Hq * Dq];  // staging: raw projection [B*S, Hh*D]
__device__ float g_q[(size_t)Bq * Hq * Sq * Dq];     // [B,H,S,D]
__device__ float g_k[(size_t)Bq * KVq * Sq * Dq];    // [B,KV,S,D]
__device__ float g_v[(size_t)Bq * KVq * Sq * Dq];    // [B,KV,S,D]
__device__ float g_attn[(size_t)Bq * Sq * Hq * Dq];  // [B,S,H*D]

// ---------------------------------------------------------------------------
// TF32 tensor-core NT GEMM: C[m,n] = sum_k A[m,k] * W[n,k]
// BM=BN=128, BK=16, 256 threads (8 warps), warp tile 64x32 via mma.sync
// m16n8k8.tf32 (fp32 accumulate). Smem padded to ld=17.
// asel: 1 -> A = g_attn. csel: 1 -> C = g_proj.
// M, N multiples of 128; K multiple of 16.
// ---------------------------------------------------------------------------
__device__ __forceinline__ uint32_t f2tf32(float x) {
    uint32_t r;
    asm("cvt.rna.tf32.f32 %0, %1;" : "=r"(r) : "f"(x));
    return r;
}

__device__ __forceinline__ void mma_tf32(float& d0, float& d1, float& d2, float& d3,
                                         uint32_t a0, uint32_t a1, uint32_t a2, uint32_t a3,
                                         uint32_t b0, uint32_t b1) {
    asm volatile(
        "mma.sync.aligned.m16n8k8.row.col.f32.tf32.tf32.f32 "
        "{%0,%1,%2,%3}, {%4,%5,%6,%7}, {%8,%9}, {%0,%1,%2,%3};"
        : "+f"(d0), "+f"(d1), "+f"(d2), "+f"(d3)
        : "r"(a0), "r"(a1), "r"(a2), "r"(a3), "r"(b0), "r"(b1));
}

#define GLD 17   // smem leading dim for [128][16] tiles (pad vs bank conflicts)

__global__ __launch_bounds__(256)
void gemm_tc(const float* __restrict__ Aparam, const float* __restrict__ W,
             float* __restrict__ Cparam, int M, int N, int K,
             int asel, int csel)
{
    __shared__ uint32_t As[128 * GLD];   // A tile [m][k], tf32 bits
    __shared__ uint32_t Bs[128 * GLD];   // W tile [n][k], tf32 bits

    const float* A = (asel == 1) ? g_attn : Aparam;
    float* C = (csel == 1) ? g_proj : Cparam;

    const int tid  = threadIdx.x;
    const int lane = tid & 31;
    const int w    = tid >> 5;          // 0..7
    const int wm   = (w >> 2) * 64;     // warp row base: 0 or 64
    const int wn   = (w & 3) * 32;      // warp col base: 0,32,64,96
    const int gid  = lane >> 2;         // 0..7
    const int tig  = lane & 3;          // 0..3

    const int m0 = blockIdx.y * 128;
    const int n0 = blockIdx.x * 128;

    // Global-load mapping: 2 float4 each for A and B per iteration.
    // linear l in [0,512): row = l>>2, c4 = (l&3)*4
    const int r0 = tid >> 2;                 // rows for l = tid
    const int c0 = (tid & 3) << 2;
    const int r1 = (tid + 256) >> 2;         // rows for l = tid+256
    const int c1 = ((tid + 256) & 3) << 2;   // == c0, rows offset by 64

    const float* Arow0 = A + (size_t)(m0 + r0) * K + c0;
    const float* Arow1 = A + (size_t)(m0 + r1) * K + c1;
    const float* Wrow0 = W + (size_t)(n0 + r0) * K + c0;
    const float* Wrow1 = W + (size_t)(n0 + r1) * K + c1;

    float acc[4][4][4];
#pragma unroll
    for (int mt = 0; mt < 4; mt++)
#pragma unroll
        for (int nt = 0; nt < 4; nt++)
#pragma unroll
            for (int e = 0; e < 4; e++) acc[mt][nt][e] = 0.f;

    for (int k0 = 0; k0 < K; k0 += 16) {
        const float4 a0v = *(const float4*)(Arow0 + k0);
        const float4 a1v = *(const float4*)(Arow1 + k0);
        const float4 b0v = *(const float4*)(Wrow0 + k0);
        const float4 b1v = *(const float4*)(Wrow1 + k0);
        __syncthreads();   // previous iteration's compute reads done
        As[r0 * GLD + c0 + 0] = f2tf32(a0v.x);
        As[r0 * GLD + c0 + 1] = f2tf32(a0v.y);
        As[r0 * GLD + c0 + 2] = f2tf32(a0v.z);
        As[r0 * GLD + c0 + 3] = f2tf32(a0v.w);
        As[r1 * GLD + c1 + 0] = f2tf32(a1v.x);
        As[r1 * GLD + c1 + 1] = f2tf32(a1v.y);
        As[r1 * GLD + c1 + 2] = f2tf32(a1v.z);
        As[r1 * GLD + c1 + 3] = f2tf32(a1v.w);
        Bs[r0 * GLD + c0 + 0] = f2tf32(b0v.x);
        Bs[r0 * GLD + c0 + 1] = f2tf32(b0v.y);
        Bs[r0 * GLD + c0 + 2] = f2tf32(b0v.z);
        Bs[r0 * GLD + c0 + 3] = f2tf32(b0v.w);
        Bs[r1 * GLD + c1 + 0] = f2tf32(b1v.x);
        Bs[r1 * GLD + c1 + 1] = f2tf32(b1v.y);
        Bs[r1 * GLD + c1 + 2] = f2tf32(b1v.z);
        Bs[r1 * GLD + c1 + 3] = f2tf32(b1v.w);
        __syncthreads();

#pragma unroll
        for (int ks = 0; ks < 16; ks += 8) {
            // A fragments: 4 m-subtiles of 16 rows
            uint32_t af[4][4];
#pragma unroll
            for (int mt = 0; mt < 4; mt++) {
                const int rbase = wm + mt * 16 + gid;
                af[mt][0] = As[(rbase    ) * GLD + ks + tig    ];
                af[mt][1] = As[(rbase + 8) * GLD + ks + tig    ];
                af[mt][2] = As[(rbase    ) * GLD + ks + tig + 4];
                af[mt][3] = As[(rbase + 8) * GLD + ks + tig + 4];
            }
            // B fragments: 4 n-subtiles of 8 cols
            uint32_t bf[4][2];
#pragma unroll
            for (int nt = 0; nt < 4; nt++) {
                const int nrow = wn + nt * 8 + gid;
                bf[nt][0] = Bs[nrow * GLD + ks + tig    ];
                bf[nt][1] = Bs[nrow * GLD + ks + tig + 4];
            }
#pragma unroll
            for (int mt = 0; mt < 4; mt++)
#pragma unroll
                for (int nt = 0; nt < 4; nt++)
                    mma_tf32(acc[mt][nt][0], acc[mt][nt][1],
                             acc[mt][nt][2], acc[mt][nt][3],
                             af[mt][0], af[mt][1], af[mt][2], af[mt][3],
                             bf[nt][0], bf[nt][1]);
        }
    }

    // Epilogue: acc[mt][nt] regs map to
    //   (row = gid | gid+8, col = 2*tig | 2*tig+1) within the 16x8 subtile.
#pragma unroll
    for (int mt = 0; mt < 4; mt++) {
#pragma unroll
        for (int nt = 0; nt < 4; nt++) {
            const int n = n0 + wn + nt * 8 + 2 * tig;
            const int mA = m0 + wm + mt * 16 + gid;
            float2 v01; v01.x = acc[mt][nt][0]; v01.y = acc[mt][nt][1];
            float2 v23; v23.x = acc[mt][nt][2]; v23.y = acc[mt][nt][3];
            *(float2*)(C + (size_t)mA * N + n)       = v01;
            *(float2*)(C + (size_t)(mA + 8) * N + n) = v23;
        }
    }
}

// ---------------------------------------------------------------------------
// RoPE + transpose (unchanged - PASSING)
// ---------------------------------------------------------------------------
__global__ __launch_bounds__(256)
void rope_transpose(const float* __restrict__ cosp, const float* __restrict__ sinp,
                    int Hh, int rope, int dsel, size_t total_pairs)
{
    size_t idx = (size_t)blockIdx.x * blockDim.x + threadIdx.x;
    if (idx >= total_pairs) return;

    const int dpair = (int)(idx % (Dq / 2));
    size_t rest = idx / (Dq / 2);
    const int hh = (int)(rest % Hh);  rest /= Hh;
    const int s  = (int)(rest % Sq);
    const int b  = (int)(rest / Sq);
    const int d  = dpair * 2;

    const size_t src = ((size_t)(b * Sq + s) * Hh + hh) * Dq + d;
    float v0 = g_proj[src];
    float v1 = g_proj[src + 1];
    if (rope) {
        const float c  = cosp[s * Dq + d];
        const float sn = sinp[s * Dq + d];
        const float t0 = v0 * c - v1 * sn;
        const float t1 = v1 * c + v0 * sn;
        v0 = t0; v1 = t1;
    }
    float* dst = (dsel == 0) ? g_q : (dsel == 1) ? g_k : g_v;
    const size_t o = (((size_t)b * Hh + hh) * Sq + s) * Dq + d;
    dst[o]     = v0;
    dst[o + 1] = v1;
}

// ---------------------------------------------------------------------------
// Flash attention v3 (unchanged - PASSING). LDP=130 (rows are 128 wide).
// ---------------------------------------------------------------------------
#define LDP 130
#define FLASH_FLOATS (64 * LDP + 32 * LDP + 32 * 128)

__global__ __launch_bounds__(256)
void flash_v3()
{
    extern __shared__ float sm[];
    float* Qs = sm;                  // [64][LDP]
    float* Ks = Qs + 64 * LDP;       // [32][LDP]; after scores reused as P[c][r]
    float* Vs = Ks + 32 * LDP;       // [32][128]

    const int qb = blockIdx.x;
    const int h  = blockIdx.y;
    const int b  = blockIdx.z;
    const int kh = h / Gq;
    const int tid = threadIdx.x;
    const int r = tid >> 2;          // query row 0..63
    const int q = tid & 3;           // quarter 0..3
    const float scale = 0.08838834764831845f;  // 1/sqrt(128)

    const float* Qg = g_q + (((size_t)b * Hq  + h ) * Sq + (size_t)qb * 64) * Dq;
    const float* Kg = g_k + (((size_t)b * KVq + kh) * Sq) * Dq;
    const float* Vg = g_v + (((size_t)b * KVq + kh) * Sq) * Dq;

#pragma unroll
    for (int i = 0; i < 8; i++) {
        const int idx = tid + i * 256;
        const int rr = idx >> 5;
        const int c4 = (idx & 31) << 2;
        float4 v = *(const float4*)(Qg + rr * Dq + c4);
        Qs[rr * LDP + c4 + 0] = v.x;
        Qs[rr * LDP + c4 + 1] = v.y;
        Qs[rr * LDP + c4 + 2] = v.z;
        Qs[rr * LDP + c4 + 3] = v.w;
    }

    float m_i = -INFINITY;
    float l_i = 0.f;
    float o[32];
#pragma unroll
    for (int j = 0; j < 32; j++) o[j] = 0.f;

    const int qr = qb * 64 + r;
    const int ntiles = 2 * qb + 2;

    for (int cb = 0; cb < ntiles; cb++) {
        __syncthreads();
#pragma unroll
        for (int i = 0; i < 4; i++) {
            const int idx = tid + i * 256;
            const int rr = idx >> 5;
            const int c4 = (idx & 31) << 2;
            float4 kv = *(const float4*)(Kg + (size_t)(cb * 32 + rr) * Dq + c4);
            Ks[rr * LDP + c4 + 0] = kv.x;
            Ks[rr * LDP + c4 + 1] = kv.y;
            Ks[rr * LDP + c4 + 2] = kv.z;
            Ks[rr * LDP + c4 + 3] = kv.w;
            float4 vv = *(const float4*)(Vg + (size_t)(cb * 32 + rr) * Dq + c4);
            *(float4*)(Vs + rr * 128 + c4) = vv;
        }
        __syncthreads();

        float s8[8];
#pragma unroll
        for (int j = 0; j < 8; j++) s8[j] = 0.f;
        const float* qrow = Qs + r * LDP;
#pragma unroll 4
        for (int k = 0; k < 128; k++) {
            const float qv = qrow[k];
#pragma unroll
            for (int j = 0; j < 8; j++)
                s8[j] += qv * Ks[(q * 8 + j) * LDP + k];
        }
        __syncthreads();

        float mx = -INFINITY;
#pragma unroll
        for (int j = 0; j < 8; j++) {
            const int kc = cb * 32 + q * 8 + j;
            s8[j] = (kc <= qr) ? s8[j] * scale : -INFINITY;
            mx = fmaxf(mx, s8[j]);
        }
        mx = fmaxf(mx, __shfl_xor_sync(0xffffffffu, mx, 1));
        mx = fmaxf(mx, __shfl_xor_sync(0xffffffffu, mx, 2));
        const float m_new = fmaxf(m_i, mx);
        const float corr  = __expf(m_i - m_new);
        float lsum = 0.f;
#pragma unroll
        for (int j = 0; j < 8; j++) {
            s8[j] = __expf(s8[j] - m_new);
            lsum += s8[j];
        }
        lsum += __shfl_xor_sync(0xffffffffu, lsum, 1);
        lsum += __shfl_xor_sync(0xffffffffu, lsum, 2);
        l_i = l_i * corr + lsum;
        m_i = m_new;
#pragma unroll
        for (int j = 0; j < 32; j++) o[j] *= corr;
#pragma unroll
        for (int j = 0; j < 8; j++)
            Ks[(q * 8 + j) * LDP + r] = s8[j];
        __syncthreads();

        for (int c = 0; c < 32; c++) {
            const float pv = Ks[c * LDP + r];
            const float* vrow = Vs + c * 128 + q * 4;
#pragma unroll
            for (int j = 0; j < 8; j++) {
                float4 v4 = *(const float4*)(vrow + j * 16);
                o[j * 4 + 0] += pv * v4.x;
                o[j * 4 + 1] += pv * v4.y;
                o[j * 4 + 2] += pv * v4.z;
                o[j * 4 + 3] += pv * v4.w;
            }
        }
    }

    const float inv = 1.f / l_i;
    float* og = g_attn + ((size_t)(b * Sq + qr) * Hq + h) * Dq + q * 4;
#pragma unroll
    for (int j = 0; j < 8; j++) {
        float4 v;
        v.x = o[j * 4 + 0] * inv;
        v.y = o[j * 4 + 1] * inv;
        v.z = o[j * 4 + 2] * inv;
        v.w = o[j * 4 + 3] * inv;
        *(float4*)(og + j * 16) = v;
    }
}

// ---------------------------------------------------------------------------
// Launcher
// ---------------------------------------------------------------------------
extern "C" void kernel_launch(void* const* d_in, const int* in_sizes, int n_in,
                              void* d_out, int out_size)
{
    const float *hs, *cosp, *sinp, *wq, *wk, *wv, *wo;
    if (in_sizes[0] == Bq * Sq * HIDq) {
        hs   = (const float*)d_in[0];
        cosp = (const float*)d_in[1];
        sinp = (const float*)d_in[2];
        wq   = (const float*)d_in[3];
        wk   = (const float*)d_in[4];
        wv   = (const float*)d_in[5];
        wo   = (const float*)d_in[6];
    } else {  // alphabetical fallback
        cosp = (const float*)d_in[0];
        hs   = (const float*)d_in[1];
        sinp = (const float*)d_in[2];
        wk   = (const float*)d_in[3];
        wo   = (const float*)d_in[4];
        wq   = (const float*)d_in[5];
        wv   = (const float*)d_in[6];
    }
    float* out = (float*)d_out;

    const dim3 blk(256);
    const int M = Bq * Sq;          // 4096
    const int NQ = Hq * Dq;         // 4096
    const int NKV = KVq * Dq;       // 1024

    // Q projection -> g_proj, then RoPE+transpose -> g_q
    gemm_tc<<<dim3(NQ / 128, M / 128), blk>>>(hs, wq, nullptr, M, NQ, HIDq, 0, 1);
    {
        size_t pairs = (size_t)Bq * Sq * Hq * (Dq / 2);
        rope_transpose<<<(unsigned)((pairs + 255) / 256), 256>>>(cosp, sinp, Hq, 1, 0, pairs);
    }
    // K projection -> g_proj, then RoPE+transpose -> g_k
    gemm_tc<<<dim3(NKV / 128, M / 128), blk>>>(hs, wk, nullptr, M, NKV, HIDq, 0, 1);
    {
        size_t pairs = (size_t)Bq * Sq * KVq * (Dq / 2);
        rope_transpose<<<(unsigned)((pairs + 255) / 256), 256>>>(cosp, sinp, KVq, 1, 1, pairs);
    }
    // V projection -> g_proj, then transpose -> g_v
    gemm_tc<<<dim3(NKV / 128, M / 128), blk>>>(hs, wv, nullptr, M, NKV, HIDq, 0, 1);
    {
        size_t pairs = (size_t)Bq * Sq * KVq * (Dq / 2);
        rope_transpose<<<(unsigned)((pairs + 255) / 256), 256>>>(cosp, sinp, KVq, 0, 2, pairs);
    }

    // Flash attention v3 -> g_attn
    const int smem_bytes = FLASH_FLOATS * (int)sizeof(float);  // 66,304
    cudaFuncSetAttribute(flash_v3, cudaFuncAttributeMaxDynamicSharedMemorySize,
                         smem_bytes);
    flash_v3<<<dim3(Sq / 64, Hq, Bq), blk, smem_bytes>>>();

    // Output projection: out = g_attn @ wo^T
    gemm_tc<<<dim3(HIDq / 128, M / 128), blk>>>(nullptr, wo, out, M, HIDq, NQ, 1, 0);
}

// round 11
// speedup vs baseline: 16.3678x; 1.0719x over previous
#include <cuda_runtime.h>
#include <math.h>
#include <stdint.h>

// Problem constants
#define Bq   2
#define Sq   2048
#define HIDq 4096
#define Hq   32
#define KVq  8
#define Dq   128
#define Gq   (Hq / KVq)

// Scratch buffers (allocation-free rule: __device__ globals)
__device__ float g_proj[(size_t)Bq * Sq * Hq * Dq];  // staging: raw projection [B*S, Hh*D]
__device__ float g_q[(size_t)Bq * Hq * Sq * Dq];     // [B,H,S,D]
__device__ float g_k[(size_t)Bq * KVq * Sq * Dq];    // [B,KV,S,D]
__device__ float g_v[(size_t)Bq * KVq * Sq * Dq];    // [B,KV,S,D]
__device__ float g_attn[(size_t)Bq * Sq * Hq * Dq];  // [B,S,H*D]

// ---------------------------------------------------------------------------
// TF32 tensor-core NT GEMM, double-buffered.
// C[m,n] = sum_k A[m,k] * W[n,k]
// BM=BN=128, BK=16, 256 threads (8 warps), warp tile 64x32 via
// mma.sync.m16n8k8.tf32 (fp32 accumulate).
// Smem ld GLD=20: fragment LDS conflict-free (banks (20*gid+tig)%32 all
// distinct) and 16B-aligned rows for STS.128.
// asel: 1 -> A = g_attn. csel: 1 -> C = g_proj.
// ---------------------------------------------------------------------------
__device__ __forceinline__ uint32_t f2tf32(float x) {
    uint32_t r;
    asm("cvt.rna.tf32.f32 %0, %1;" : "=r"(r) : "f"(x));
    return r;
}

__device__ __forceinline__ uint4 pack_tf32(float4 v) {
    uint4 r;
    r.x = f2tf32(v.x);
    r.y = f2tf32(v.y);
    r.z = f2tf32(v.z);
    r.w = f2tf32(v.w);
    return r;
}

__device__ __forceinline__ void mma_tf32(float& d0, float& d1, float& d2, float& d3,
                                         uint32_t a0, uint32_t a1, uint32_t a2, uint32_t a3,
                                         uint32_t b0, uint32_t b1) {
    asm volatile(
        "mma.sync.aligned.m16n8k8.row.col.f32.tf32.tf32.f32 "
        "{%0,%1,%2,%3}, {%4,%5,%6,%7}, {%8,%9}, {%0,%1,%2,%3};"
        : "+f"(d0), "+f"(d1), "+f"(d2), "+f"(d3)
        : "r"(a0), "r"(a1), "r"(a2), "r"(a3), "r"(b0), "r"(b1));
}

#define GLD 20

__global__ __launch_bounds__(256)
void gemm_tc(const float* __restrict__ Aparam, const float* __restrict__ W,
             float* __restrict__ Cparam, int M, int N, int K,
             int asel, int csel)
{
    __shared__ uint32_t As[2][128 * GLD];   // A tile [m][k], tf32 bits, 2 stages
    __shared__ uint32_t Bs[2][128 * GLD];   // W tile [n][k]

    const float* A = (asel == 1) ? g_attn : Aparam;
    float* C = (csel == 1) ? g_proj : Cparam;

    const int tid  = threadIdx.x;
    const int lane = tid & 31;
    const int w    = tid >> 5;          // 0..7
    const int wm   = (w >> 2) * 64;     // warp row base: 0 or 64
    const int wn   = (w & 3) * 32;      // warp col base: 0,32,64,96
    const int gid  = lane >> 2;         // 0..7
    const int tig  = lane & 3;          // 0..3

    const int m0 = blockIdx.y * 128;
    const int n0 = blockIdx.x * 128;

    // Global-load mapping: 2 float4 each for A and B per iteration.
    const int r0 = tid >> 2;                 // 0..63
    const int c0 = (tid & 3) << 2;           // 0,4,8,12
    const int r1 = r0 + 64;                  // 64..127

    const float* Arow0 = A + (size_t)(m0 + r0) * K + c0;
    const float* Arow1 = A + (size_t)(m0 + r1) * K + c0;
    const float* Wrow0 = W + (size_t)(n0 + r0) * K + c0;
    const float* Wrow1 = W + (size_t)(n0 + r1) * K + c0;

    float acc[4][4][4];
#pragma unroll
    for (int mt = 0; mt < 4; mt++)
#pragma unroll
        for (int nt = 0; nt < 4; nt++)
#pragma unroll
            for (int e = 0; e < 4; e++) acc[mt][nt][e] = 0.f;

    const int niter = K >> 4;   // K/16

    // Prologue: stage 0
    {
        float4 a0v = *(const float4*)(Arow0);
        float4 a1v = *(const float4*)(Arow1);
        float4 b0v = *(const float4*)(Wrow0);
        float4 b1v = *(const float4*)(Wrow1);
        *(uint4*)&As[0][r0 * GLD + c0] = pack_tf32(a0v);
        *(uint4*)&As[0][r1 * GLD + c0] = pack_tf32(a1v);
        *(uint4*)&Bs[0][r0 * GLD + c0] = pack_tf32(b0v);
        *(uint4*)&Bs[0][r1 * GLD + c0] = pack_tf32(b1v);
    }
    __syncthreads();

    for (int i = 0; i < niter; i++) {
        const int cur = i & 1;
        const int nxt = cur ^ 1;

        // Prefetch next tile (global loads issue early, land during compute)
        float4 a0v, a1v, b0v, b1v;
        const bool more = (i + 1) < niter;
        if (more) {
            const int k0 = (i + 1) << 4;
            a0v = *(const float4*)(Arow0 + k0);
            a1v = *(const float4*)(Arow1 + k0);
            b0v = *(const float4*)(Wrow0 + k0);
            b1v = *(const float4*)(Wrow1 + k0);
        }

        // Compute on current stage
        const uint32_t* Ac = As[cur];
        const uint32_t* Bc = Bs[cur];
#pragma unroll
        for (int ks = 0; ks < 16; ks += 8) {
            uint32_t af[4][4];
#pragma unroll
            for (int mt = 0; mt < 4; mt++) {
                const int rbase = wm + mt * 16 + gid;
                af[mt][0] = Ac[(rbase    ) * GLD + ks + tig    ];
                af[mt][1] = Ac[(rbase + 8) * GLD + ks + tig    ];
                af[mt][2] = Ac[(rbase    ) * GLD + ks + tig + 4];
                af[mt][3] = Ac[(rbase + 8) * GLD + ks + tig + 4];
            }
            uint32_t bf[4][2];
#pragma unroll
            for (int nt = 0; nt < 4; nt++) {
                const int nrow = wn + nt * 8 + gid;
                bf[nt][0] = Bc[nrow * GLD + ks + tig    ];
                bf[nt][1] = Bc[nrow * GLD + ks + tig + 4];
            }
#pragma unroll
            for (int mt = 0; mt < 4; mt++)
#pragma unroll
                for (int nt = 0; nt < 4; nt++)
                    mma_tf32(acc[mt][nt][0], acc[mt][nt][1],
                             acc[mt][nt][2], acc[mt][nt][3],
                             af[mt][0], af[mt][1], af[mt][2], af[mt][3],
                             bf[nt][0], bf[nt][1]);
        }

        // Stage next tile; one barrier per iteration.
        if (more) {
            *(uint4*)&As[nxt][r0 * GLD + c0] = pack_tf32(a0v);
            *(uint4*)&As[nxt][r1 * GLD + c0] = pack_tf32(a1v);
            *(uint4*)&Bs[nxt][r0 * GLD + c0] = pack_tf32(b0v);
            *(uint4*)&Bs[nxt][r1 * GLD + c0] = pack_tf32(b1v);
            __syncthreads();
        }
    }

    // Epilogue: (row = gid | gid+8, col = 2*tig | 2*tig+1) per 16x8 subtile.
#pragma unroll
    for (int mt = 0; mt < 4; mt++) {
#pragma unroll
        for (int nt = 0; nt < 4; nt++) {
            const int n = n0 + wn + nt * 8 + 2 * tig;
            const int mA = m0 + wm + mt * 16 + gid;
            float2 v01; v01.x = acc[mt][nt][0]; v01.y = acc[mt][nt][1];
            float2 v23; v23.x = acc[mt][nt][2]; v23.y = acc[mt][nt][3];
            *(float2*)(C + (size_t)mA * N + n)       = v01;
            *(float2*)(C + (size_t)(mA + 8) * N + n) = v23;
        }
    }
}

// ---------------------------------------------------------------------------
// RoPE + transpose (unchanged - PASSING)
// ---------------------------------------------------------------------------
__global__ __launch_bounds__(256)
void rope_transpose(const float* __restrict__ cosp, const float* __restrict__ sinp,
                    int Hh, int rope, int dsel, size_t total_pairs)
{
    size_t idx = (size_t)blockIdx.x * blockDim.x + threadIdx.x;
    if (idx >= total_pairs) return;

    const int dpair = (int)(idx % (Dq / 2));
    size_t rest = idx / (Dq / 2);
    const int hh = (int)(rest % Hh);  rest /= Hh;
    const int s  = (int)(rest % Sq);
    const int b  = (int)(rest / Sq);
    const int d  = dpair * 2;

    const size_t src = ((size_t)(b * Sq + s) * Hh + hh) * Dq + d;
    float v0 = g_proj[src];
    float v1 = g_proj[src + 1];
    if (rope) {
        const float c  = cosp[s * Dq + d];
        const float sn = sinp[s * Dq + d];
        const float t0 = v0 * c - v1 * sn;
        const float t1 = v1 * c + v0 * sn;
        v0 = t0; v1 = t1;
    }
    float* dst = (dsel == 0) ? g_q : (dsel == 1) ? g_k : g_v;
    const size_t o = (((size_t)b * Hh + hh) * Sq + s) * Dq + d;
    dst[o]     = v0;
    dst[o + 1] = v1;
}

// ---------------------------------------------------------------------------
// Flash attention v3 (unchanged - PASSING). LDP=130 (rows are 128 wide).
// ---------------------------------------------------------------------------
#define LDP 130
#define FLASH_FLOATS (64 * LDP + 32 * LDP + 32 * 128)

__global__ __launch_bounds__(256)
void flash_v3()
{
    extern __shared__ float sm[];
    float* Qs = sm;                  // [64][LDP]
    float* Ks = Qs + 64 * LDP;       // [32][LDP]; after scores reused as P[c][r]
    float* Vs = Ks + 32 * LDP;       // [32][128]

    const int qb = blockIdx.x;
    const int h  = blockIdx.y;
    const int b  = blockIdx.z;
    const int kh = h / Gq;
    const int tid = threadIdx.x;
    const int r = tid >> 2;          // query row 0..63
    const int q = tid & 3;           // quarter 0..3
    const float scale = 0.08838834764831845f;  // 1/sqrt(128)

    const float* Qg = g_q + (((size_t)b * Hq  + h ) * Sq + (size_t)qb * 64) * Dq;
    const float* Kg = g_k + (((size_t)b * KVq + kh) * Sq) * Dq;
    const float* Vg = g_v + (((size_t)b * KVq + kh) * Sq) * Dq;

#pragma unroll
    for (int i = 0; i < 8; i++) {
        const int idx = tid + i * 256;
        const int rr = idx >> 5;
        const int c4 = (idx & 31) << 2;
        float4 v = *(const float4*)(Qg + rr * Dq + c4);
        Qs[rr * LDP + c4 + 0] = v.x;
        Qs[rr * LDP + c4 + 1] = v.y;
        Qs[rr * LDP + c4 + 2] = v.z;
        Qs[rr * LDP + c4 + 3] = v.w;
    }

    float m_i = -INFINITY;
    float l_i = 0.f;
    float o[32];
#pragma unroll
    for (int j = 0; j < 32; j++) o[j] = 0.f;

    const int qr = qb * 64 + r;
    const int ntiles = 2 * qb + 2;

    for (int cb = 0; cb < ntiles; cb++) {
        __syncthreads();
#pragma unroll
        for (int i = 0; i < 4; i++) {
            const int idx = tid + i * 256;
            const int rr = idx >> 5;
            const int c4 = (idx & 31) << 2;
            float4 kv = *(const float4*)(Kg + (size_t)(cb * 32 + rr) * Dq + c4);
            Ks[rr * LDP + c4 + 0] = kv.x;
            Ks[rr * LDP + c4 + 1] = kv.y;
            Ks[rr * LDP + c4 + 2] = kv.z;
            Ks[rr * LDP + c4 + 3] = kv.w;
            float4 vv = *(const float4*)(Vg + (size_t)(cb * 32 + rr) * Dq + c4);
            *(float4*)(Vs + rr * 128 + c4) = vv;
        }
        __syncthreads();

        float s8[8];
#pragma unroll
        for (int j = 0; j < 8; j++) s8[j] = 0.f;
        const float* qrow = Qs + r * LDP;
#pragma unroll 4
        for (int k = 0; k < 128; k++) {
            const float qv = qrow[k];
#pragma unroll
            for (int j = 0; j < 8; j++)
                s8[j] += qv * Ks[(q * 8 + j) * LDP + k];
        }
        __syncthreads();

        float mx = -INFINITY;
#pragma unroll
        for (int j = 0; j < 8; j++) {
            const int kc = cb * 32 + q * 8 + j;
            s8[j] = (kc <= qr) ? s8[j] * scale : -INFINITY;
            mx = fmaxf(mx, s8[j]);
        }
        mx = fmaxf(mx, __shfl_xor_sync(0xffffffffu, mx, 1));
        mx = fmaxf(mx, __shfl_xor_sync(0xffffffffu, mx, 2));
        const float m_new = fmaxf(m_i, mx);
        const float corr  = __expf(m_i - m_new);
        float lsum = 0.f;
#pragma unroll
        for (int j = 0; j < 8; j++) {
            s8[j] = __expf(s8[j] - m_new);
            lsum += s8[j];
        }
        lsum += __shfl_xor_sync(0xffffffffu, lsum, 1);
        lsum += __shfl_xor_sync(0xffffffffu, lsum, 2);
        l_i = l_i * corr + lsum;
        m_i = m_new;
#pragma unroll
        for (int j = 0; j < 32; j++) o[j] *= corr;
#pragma unroll
        for (int j = 0; j < 8; j++)
            Ks[(q * 8 + j) * LDP + r] = s8[j];
        __syncthreads();

        for (int c = 0; c < 32; c++) {
            const float pv = Ks[c * LDP + r];
            const float* vrow = Vs + c * 128 + q * 4;
#pragma unroll
            for (int j = 0; j < 8; j++) {
                float4 v4 = *(const float4*)(vrow + j * 16);
                o[j * 4 + 0] += pv * v4.x;
                o[j * 4 + 1] += pv * v4.y;
                o[j * 4 + 2] += pv * v4.z;
                o[j * 4 + 3] += pv * v4.w;
            }
        }
    }

    const float inv = 1.f / l_i;
    float* og = g_attn + ((size_t)(b * Sq + qr) * Hq + h) * Dq + q * 4;
#pragma unroll
    for (int j = 0; j < 8; j++) {
        float4 v;
        v.x = o[j * 4 + 0] * inv;
        v.y = o[j * 4 + 1] * inv;
        v.z = o[j * 4 + 2] * inv;
        v.w = o[j * 4 + 3] * inv;
        *(float4*)(og + j * 16) = v;
    }
}

// ---------------------------------------------------------------------------
// Launcher
// ---------------------------------------------------------------------------
extern "C" void kernel_launch(void* const* d_in, const int* in_sizes, int n_in,
                              void* d_out, int out_size)
{
    const float *hs, *cosp, *sinp, *wq, *wk, *wv, *wo;
    if (in_sizes[0] == Bq * Sq * HIDq) {
        hs   = (const float*)d_in[0];
        cosp = (const float*)d_in[1];
        sinp = (const float*)d_in[2];
        wq   = (const float*)d_in[3];
        wk   = (const float*)d_in[4];
        wv   = (const float*)d_in[5];
        wo   = (const float*)d_in[6];
    } else {  // alphabetical fallback
        cosp = (const float*)d_in[0];
        hs   = (const float*)d_in[1];
        sinp = (const float*)d_in[2];
        wk   = (const float*)d_in[3];
        wo   = (const float*)d_in[4];
        wq   = (const float*)d_in[5];
        wv   = (const float*)d_in[6];
    }
    float* out = (float*)d_out;

    const dim3 blk(256);
    const int M = Bq * Sq;          // 4096
    const int NQ = Hq * Dq;         // 4096
    const int NKV = KVq * Dq;       // 1024

    // Q projection -> g_proj, then RoPE+transpose -> g_q
    gemm_tc<<<dim3(NQ / 128, M / 128), blk>>>(hs, wq, nullptr, M, NQ, HIDq, 0, 1);
    {
        size_t pairs = (size_t)Bq * Sq * Hq * (Dq / 2);
        rope_transpose<<<(unsigned)((pairs + 255) / 256), 256>>>(cosp, sinp, Hq, 1, 0, pairs);
    }
    // K projection -> g_proj, then RoPE+transpose -> g_k
    gemm_tc<<<dim3(NKV / 128, M / 128), blk>>>(hs, wk, nullptr, M, NKV, HIDq, 0, 1);
    {
        size_t pairs = (size_t)Bq * Sq * KVq * (Dq / 2);
        rope_transpose<<<(unsigned)((pairs + 255) / 256), 256>>>(cosp, sinp, KVq, 1, 1, pairs);
    }
    // V projection -> g_proj, then transpose -> g_v
    gemm_tc<<<dim3(NKV / 128, M / 128), blk>>>(hs, wv, nullptr, M, NKV, HIDq, 0, 1);
    {
        size_t pairs = (size_t)Bq * Sq * KVq * (Dq / 2);
        rope_transpose<<<(unsigned)((pairs + 255) / 256), 256>>>(cosp, sinp, KVq, 0, 2, pairs);
    }

    // Flash attention v3 -> g_attn
    const int smem_bytes = FLASH_FLOATS * (int)sizeof(float);  // 66,304
    cudaFuncSetAttribute(flash_v3, cudaFuncAttributeMaxDynamicSharedMemorySize,
                         smem_bytes);
    flash_v3<<<dim3(Sq / 64, Hq, Bq), blk, smem_bytes>>>();

    // Output projection: out = g_attn @ wo^T
    gemm_tc<<<dim3(HIDq / 128, M / 128), blk>>>(nullptr, wo, out, M, HIDq, NQ, 1, 0);
}